// round 15
// baseline (speedup 1.0000x reference)
#include <cuda_runtime.h>
#include <cuda_fp16.h>
#include <math.h>
#include <stdint.h>

#define B_ 1024
#define D_ 1024
#define H_ 4096
#define C_ 5120
#define LN_EPS 1e-3f
#define KSLICE_D 4

// ---------------- scratch (device globals: allocation-free) ----------------
__device__ __align__(1024) __half g_a1[B_ * C_];
__device__ __align__(1024) __half g_a2[B_ * C_];
__device__ __align__(1024) __half g_a3[B_ * H_];
__device__ __align__(1024) __half g_wu[(long)H_ * C_];
__device__ __align__(1024) __half g_wr[(long)H_ * C_];
__device__ __align__(1024) __half g_wg[(long)H_ * C_];
__device__ __align__(1024) __half g_wp[(long)H_ * C_];
__device__ __align__(1024) __half g_wd[(long)D_ * H_];
__device__ __align__(1024) __half g_u [B_ * H_];
__device__ __align__(1024) __half g_g [B_ * H_];
__device__ __align__(1024) __half g_up[B_ * H_];
__device__ float g_nh[B_ * H_];
__device__ float g_do[KSLICE_D * B_ * D_];

// ---------------- helpers ----------------
__device__ __forceinline__ uint32_t smem_u32(const void* p) {
    uint32_t a;
    asm("{ .reg .u64 t; cvta.to.shared.u64 t, %1; cvt.u32.u64 %0, t; }" : "=r"(a) : "l"(p));
    return a;
}
__device__ __forceinline__ void cp16(uint32_t dst, const void* src) {
    asm volatile("cp.async.cg.shared.global [%0], [%1], 16;" :: "r"(dst), "l"(src) : "memory");
}
__device__ __forceinline__ void ldsm_x4(uint32_t* r, uint32_t addr) {
    asm volatile("ldmatrix.sync.aligned.m8n8.x4.shared.b16 {%0,%1,%2,%3}, [%4];"
                 : "=r"(r[0]), "=r"(r[1]), "=r"(r[2]), "=r"(r[3]) : "r"(addr));
}
__device__ __forceinline__ void mma_f32(float* c, const uint32_t* a, uint32_t b0, uint32_t b1) {
    asm volatile(
        "mma.sync.aligned.m16n8k16.row.col.f32.f16.f16.f32 "
        "{%0,%1,%2,%3}, {%4,%5,%6,%7}, {%8,%9}, {%0,%1,%2,%3};"
        : "+f"(c[0]), "+f"(c[1]), "+f"(c[2]), "+f"(c[3])
        : "r"(a[0]), "r"(a[1]), "r"(a[2]), "r"(a[3]), "r"(b0), "r"(b1));
}
__device__ __forceinline__ float sigm(float x) { return 1.0f / (1.0f + expf(-x)); }

// swizzled offset inside a [rows][32 fp16] tile (64B rows, 16B chunks) — R11-proven
__device__ __forceinline__ uint32_t sw_off(int row, int cb) {
    return (uint32_t)row * 64u + (uint32_t)((cb ^ ((row >> 1) & 3)) << 4);
}

// ---------------- shared tconv body (transpose + fp16 round, 64K x 32N tile) ----------------
__device__ __forceinline__ void tconv_body(const float* __restrict__ src,
                                           __half* __restrict__ dst,
                                           int kdim, int ndim, int idx, void* smem)
{
    float (*t)[33] = reinterpret_cast<float(*)[33]>(smem);
    const int nblk = ndim / 32;
    const int nb = (idx % nblk) * 32;
    const int kt = (idx / nblk) * 64;
    const int tid = threadIdx.x;
    const int c4 = (tid & 7) * 4, r0 = tid >> 3;
#pragma unroll
    for (int p = 0; p < 2; p++) {
        const int r = r0 + p * 32;
        const float4 f = *(const float4*)(src + (size_t)(kt + r) * ndim + nb + c4);
        t[r][c4] = f.x; t[r][c4 + 1] = f.y; t[r][c4 + 2] = f.z; t[r][c4 + 3] = f.w;
    }
    __syncthreads();
    const int n  = tid >> 3;
    const int k8 = (tid & 7) * 8;
    __half2 hv[4];
#pragma unroll
    for (int i = 0; i < 4; i++)
        hv[i] = __halves2half2(__float2half_rn(t[k8 + 2 * i][n]), __float2half_rn(t[k8 + 2 * i + 1][n]));
    const long o = (long)(nb + n) * kdim + kt + k8;
    *(uint4*)(dst + o) = make_uint4(*(uint32_t*)&hv[0], *(uint32_t*)&hv[1],
                                    *(uint32_t*)&hv[2], *(uint32_t*)&hv[3]);
}

// ---------------- single-term fp16 HMMA GEMM + piggyback tconv ----------------
#define KT 32
#define STG 3
#define STAGE_BYTES 16384u

// MODE 0: !second -> u = sigmoid(v+b0) as fp16; second -> rh = sigmoid(v+b1)*hmul fp16 into oba concat
// MODE 1: g / up = v+bias as fp16 -> hout0 / hout1
// MODE 2: raw f32 partials -> fout0 + kz*B_*D_
template<int MODE>
__global__ void __launch_bounds__(256, 2) gemm_fused(
    const __half* __restrict__ A, int ldA,
    const __half* __restrict__ B0, const __half* __restrict__ B1, int ldB,
    const float* __restrict__ bias0, const float* __restrict__ bias1,
    const float* __restrict__ hmul,
    float* __restrict__ fout0,
    __half* __restrict__ hout0, __half* __restrict__ hout1,
    __half* __restrict__ oba,
    int K, int ntx, int mty, int nhalf, int kslices,
    const float* __restrict__ ts0, const float* __restrict__ ts1,
    __half* __restrict__ td0, __half* __restrict__ td1,
    int tkdim, int tndim, int tPerW)
{
    extern __shared__ __align__(1024) char smraw[];
    const int gb = ntx * mty * kslices;
    const int bx = blockIdx.x;

    if (bx >= gb) {
        int idx = bx - gb;
        const float* src = ts0;
        __half* dst = td0;
        if (idx >= tPerW) { src = ts1; dst = td1; idx -= tPerW; }
        tconv_body(src, dst, tkdim, tndim, idx, smraw);
        return;
    }

    const uint32_t sb = smem_u32(smraw);
    const int tid = threadIdx.x, lane = tid & 31, wid = tid >> 5;
    const int wm = (wid >> 2) * 64;
    const int wn = (wid & 3) * 32;

    const int nt = bx % ntx;
    const int mt = (bx / ntx) % mty;
    const int kz = bx / (ntx * mty);
    const bool second = nt >= nhalf;
    const int ntin = second ? nt - nhalf : nt;
    const __half* Bp = second ? B1 : B0;
    const float* bias = second ? bias1 : bias0;

    const int m0 = mt * 128, n0 = ntin * 128;
    const int Ks = K / kslices;
    const int kbeg = kz * Ks;
    const int S = Ks / KT;

    const int lr  = tid >> 1;
    const int lcb = (tid & 1) * 2;
    auto load_stage = [&](int slot, int kk) {
        const uint32_t tb = sb + (uint32_t)slot * STAGE_BYTES;
        const size_t arow = (size_t)(m0 + lr) * ldA + kk;
        const size_t brow = (size_t)(n0 + lr) * ldB + kk;
#pragma unroll
        for (int c = 0; c < 2; c++) {
            const int cb = lcb + c;
            const uint32_t sw = tb + sw_off(lr, cb);
            cp16(sw,         A  + arow + cb * 8);
            cp16(sw + 8192,  Bp + brow + cb * 8);
        }
    };

    const int lb = (lane >> 4) & 1;
    uint32_t offA[4], offB[2];
#pragma unroll
    for (int i = 0; i < 4; i++) offA[i] = sw_off(wm + i * 16 + (lane & 15), lb);
#pragma unroll
    for (int jp = 0; jp < 2; jp++) offB[jp] = sw_off(wn + jp * 16 + (lane & 15), lb);

#pragma unroll
    for (int s = 0; s < STG - 1; s++) {
        if (s < S) load_stage(s, kbeg + s * KT);
        asm volatile("cp.async.commit_group;" ::: "memory");
    }

    float acc[4][4][4];
#pragma unroll
    for (int i = 0; i < 4; i++)
#pragma unroll
        for (int j = 0; j < 4; j++)
#pragma unroll
            for (int e = 0; e < 4; e++) acc[i][j][e] = 0.f;

    for (int ks = 0; ks < S; ks++) {
        asm volatile("cp.async.wait_group 1;" ::: "memory");
        __syncthreads();
        if (ks + STG - 1 < S) load_stage((ks + STG - 1) % STG, kbeg + (ks + STG - 1) * KT);
        asm volatile("cp.async.commit_group;" ::: "memory");

        const uint32_t base = sb + (uint32_t)(ks % STG) * STAGE_BYTES;
#pragma unroll
        for (int s = 0; s < 2; s++) {
            const uint32_t sx = (uint32_t)(s << 5);
            uint32_t a[4][4], b[2][4];
#pragma unroll
            for (int i = 0; i < 4; i++)   ldsm_x4(a[i], base + (offA[i] ^ sx));
#pragma unroll
            for (int jp = 0; jp < 2; jp++) ldsm_x4(b[jp], base + 8192 + (offB[jp] ^ sx));
#pragma unroll
            for (int i = 0; i < 4; i++)
#pragma unroll
                for (int j = 0; j < 4; j++)
                    mma_f32(acc[i][j], a[i], b[j >> 1][j & 1], b[j >> 1][2 | (j & 1)]);
        }
    }

    // ---- epilogue (paired half2 stores; gc always even) ----
#pragma unroll
    for (int i = 0; i < 4; i++) {
#pragma unroll
        for (int j = 0; j < 4; j++) {
            const int r0 = m0 + wm + i * 16 + (lane >> 2);
            const int gc = ntin * 128 + wn + j * 8 + 2 * (lane & 3);
#pragma unroll
            for (int half = 0; half < 2; half++) {
                const int row = r0 + half * 8;
                const float v0r = acc[i][j][half * 2];
                const float v1r = acc[i][j][half * 2 + 1];
                if (MODE == 0) {
                    const float v0 = v0r + bias[gc], v1 = v1r + bias[gc + 1];
                    if (!second) {
                        *(__half2*)(hout0 + (long)row * H_ + gc) =
                            __halves2half2(__float2half_rn(sigm(v0)), __float2half_rn(sigm(v1)));
                    } else {
                        const float rh0 = sigm(v0) * hmul[(long)row * H_ + gc];
                        const float rh1 = sigm(v1) * hmul[(long)row * H_ + gc + 1];
                        *(__half2*)(oba + (long)row * C_ + D_ + gc) =
                            __halves2half2(__float2half_rn(rh0), __float2half_rn(rh1));
                    }
                } else if (MODE == 1) {
                    __half* dst = second ? hout1 : hout0;
                    *(__half2*)(dst + (long)row * H_ + gc) =
                        __halves2half2(__float2half_rn(v0r + bias[gc]),
                                       __float2half_rn(v1r + bias[gc + 1]));
                } else {
                    float* dst = fout0 + (size_t)kz * B_ * D_;
                    dst[(long)row * D_ + gc]     = v0r;
                    dst[(long)row * D_ + gc + 1] = v1r;
                }
            }
        }
    }
}

// ---------------- prologue: conv_a1 blocks + tconv(W_u, W_r) blocks ----------------
#define CONV_BLOCKS (B_ * C_ / 4 / 256)       // 5120
#define TCONV_BIG   ((H_ / 32) * (C_ / 64))   // 10240

__global__ void __launch_bounds__(256, 2) prologue(
    const float* __restrict__ x, const float* __restrict__ h,
    __half* __restrict__ a1, __half* __restrict__ a2,
    const float* __restrict__ wu, const float* __restrict__ wr,
    __half* __restrict__ du, __half* __restrict__ dr)
{
    __shared__ float t[64][33];
    const int bx = blockIdx.x;
    if (bx < CONV_BLOCKS) {
        const long i4 = (long)bx * 256 + threadIdx.x;
        const int row = (int)(i4 / (C_ / 4));
        const int c = (int)(i4 % (C_ / 4)) * 4;
        float4 f;
        if (c < D_) f = *(const float4*)(x + (long)row * D_ + c);
        else        f = *(const float4*)(h + (long)row * H_ + (c - D_));
        __half2 hv0 = __halves2half2(__float2half_rn(f.x), __float2half_rn(f.y));
        __half2 hv1 = __halves2half2(__float2half_rn(f.z), __float2half_rn(f.w));
        const long o = (long)row * C_ + c;
        *(uint2*)(a1 + o) = make_uint2(*(uint32_t*)&hv0, *(uint32_t*)&hv1);
        if (c < D_)
            *(uint2*)(a2 + o) = make_uint2(*(uint32_t*)&hv0, *(uint32_t*)&hv1);
        return;
    }
    int idx = bx - CONV_BLOCKS;
    const float* src = wu;
    __half* dst = du;
    if (idx >= TCONV_BIG) { src = wr; dst = dr; idx -= TCONV_BIG; }
    tconv_body(src, dst, C_, H_, idx, t);
}

// ---------------- LayerNorm kernels (vectorized) ----------------
__device__ __forceinline__ float2 h2f(uint32_t u) { return __half22float2(*(__half2*)&u); }

__global__ void ln_newh(const __half* __restrict__ u, const float* __restrict__ h,
                        const __half* __restrict__ g, const __half* __restrict__ up,
                        const float* __restrict__ gamma, const float* __restrict__ beta,
                        float* __restrict__ out, __half* __restrict__ a3)
{
    const int row = blockIdx.x, tid = threadIdx.x;
    const long base = (long)row * H_;
    float v[16];
    float s = 0.f, ss = 0.f;
#pragma unroll
    for (int i = 0; i < 4; i++) {
        const int c = (i * 256 + tid) * 4;
        const uint2 uu = *(const uint2*)(u + base + c);
        const uint2 gg = *(const uint2*)(g + base + c);
        const uint2 pp = *(const uint2*)(up + base + c);
        const float4 hh = *(const float4*)(h + base + c);
        const float2 u01 = h2f(uu.x), u23 = h2f(uu.y);
        const float2 g01 = h2f(gg.x), g23 = h2f(gg.y);
        const float2 p01 = h2f(pp.x), p23 = h2f(pp.y);
        const float uf[4] = {u01.x, u01.y, u23.x, u23.y};
        const float gf[4] = {g01.x, g01.y, g23.x, g23.y};
        const float pf[4] = {p01.x, p01.y, p23.x, p23.y};
        const float hf[4] = {hh.x, hh.y, hh.z, hh.w};
#pragma unroll
        for (int e = 0; e < 4; e++) {
            const float val = hf[e] * (2.f - uf[e]) + uf[e] * (gf[e] * sigm(gf[e])) * pf[e];
            v[i * 4 + e] = val;
            s += val; ss += val * val;
        }
    }
    __shared__ float sm[2][8];
#pragma unroll
    for (int o = 16; o > 0; o >>= 1) {
        s  += __shfl_xor_sync(0xffffffffu, s, o);
        ss += __shfl_xor_sync(0xffffffffu, ss, o);
    }
    const int warp = tid >> 5, lane = tid & 31;
    if (lane == 0) { sm[0][warp] = s; sm[1][warp] = ss; }
    __syncthreads();
    float ts = 0.f, tss = 0.f;
#pragma unroll
    for (int w = 0; w < 8; w++) { ts += sm[0][w]; tss += sm[1][w]; }
    const float mean = ts / (float)H_;
    const float var  = tss / (float)H_ - mean * mean;
    const float rstd = rsqrtf(var + LN_EPS);
#pragma unroll
    for (int i = 0; i < 4; i++) {
        const int c = (i * 256 + tid) * 4;
        const float4 gm = *(const float4*)(gamma + c);
        const float4 bt = *(const float4*)(beta + c);
        float4 r;
        r.x = (v[i * 4 + 0] - mean) * rstd * gm.x + bt.x;
        r.y = (v[i * 4 + 1] - mean) * rstd * gm.y + bt.y;
        r.z = (v[i * 4 + 2] - mean) * rstd * gm.z + bt.z;
        r.w = (v[i * 4 + 3] - mean) * rstd * gm.w + bt.w;
        *(float4*)(out + base + c) = r;
        __half2 h0 = __halves2half2(__float2half_rn(r.x), __float2half_rn(r.y));
        __half2 h1 = __halves2half2(__float2half_rn(r.z), __float2half_rn(r.w));
        *(uint2*)(a3 + base + c) = make_uint2(*(uint32_t*)&h0, *(uint32_t*)&h1);
    }
}

__global__ void ln_out(const float* __restrict__ in,
                       const float* __restrict__ bd,
                       const float* __restrict__ gamma, const float* __restrict__ beta,
                       float* __restrict__ out)
{
    const int row = blockIdx.x, tid = threadIdx.x;
    const long base = (long)row * D_;
    const long zoff = (long)B_ * D_;
    const int c = tid * 4;
    float4 val = *(const float4*)(bd + c);
#pragma unroll
    for (int z = 0; z < KSLICE_D; z++) {
        const float4 p = *(const float4*)(in + z * zoff + base + c);
        val.x += p.x; val.y += p.y; val.z += p.z; val.w += p.w;
    }
    float s = val.x + val.y + val.z + val.w;
    float ss = val.x * val.x + val.y * val.y + val.z * val.z + val.w * val.w;
    __shared__ float sm[2][8];
#pragma unroll
    for (int o = 16; o > 0; o >>= 1) {
        s  += __shfl_xor_sync(0xffffffffu, s, o);
        ss += __shfl_xor_sync(0xffffffffu, ss, o);
    }
    const int warp = tid >> 5, lane = tid & 31;
    if (lane == 0) { sm[0][warp] = s; sm[1][warp] = ss; }
    __syncthreads();
    float ts = 0.f, tss = 0.f;
#pragma unroll
    for (int w = 0; w < 8; w++) { ts += sm[0][w]; tss += sm[1][w]; }
    const float mean = ts / (float)D_;
    const float var  = tss / (float)D_ - mean * mean;
    const float rstd = rsqrtf(var + LN_EPS);
    const float4 gm = *(const float4*)(gamma + c);
    const float4 bt = *(const float4*)(beta + c);
    float4 r;
    r.x = (val.x - mean) * rstd * gm.x + bt.x;
    r.y = (val.y - mean) * rstd * gm.y + bt.y;
    r.z = (val.z - mean) * rstd * gm.z + bt.z;
    r.w = (val.w - mean) * rstd * gm.w + bt.w;
    *(float4*)(out + base + c) = r;
}

// ---------------- host ----------------
extern "C" void kernel_launch(void* const* d_in, const int* in_sizes, int n_in,
                              void* d_out, int out_size)
{
    const float* x    = (const float*)d_in[0];
    const float* h    = (const float*)d_in[1];
    const float* W_u  = (const float*)d_in[2];
    const float* b_u  = (const float*)d_in[3];
    const float* W_r  = (const float*)d_in[4];
    const float* b_r  = (const float*)d_in[5];
    const float* W_g  = (const float*)d_in[6];
    const float* b_g  = (const float*)d_in[7];
    const float* W_up = (const float*)d_in[8];
    const float* b_up = (const float*)d_in[9];
    const float* W_d  = (const float*)d_in[10];
    const float* b_d  = (const float*)d_in[11];
    const float* g_hh = (const float*)d_in[12];
    const float* be_h = (const float*)d_in[13];
    const float* g_o  = (const float*)d_in[14];
    const float* be_o = (const float*)d_in[15];
    float* out = (float*)d_out;

    void *pa1, *pa2, *pa3, *pwu, *pwr, *pwg, *pwp, *pwd, *pu, *pg, *pup;
    float *pnh, *pdo;
    cudaGetSymbolAddress(&pa1, g_a1);
    cudaGetSymbolAddress(&pa2, g_a2);
    cudaGetSymbolAddress(&pa3, g_a3);
    cudaGetSymbolAddress(&pwu, g_wu); cudaGetSymbolAddress(&pwr, g_wr);
    cudaGetSymbolAddress(&pwg, g_wg); cudaGetSymbolAddress(&pwp, g_wp);
    cudaGetSymbolAddress(&pwd, g_wd);
    cudaGetSymbolAddress(&pu,  g_u);
    cudaGetSymbolAddress(&pg,  g_g);
    cudaGetSymbolAddress(&pup, g_up);
    cudaGetSymbolAddress((void**)&pnh, g_nh);
    cudaGetSymbolAddress((void**)&pdo, g_do);

    constexpr int SMEM = STG * (int)STAGE_BYTES;  // 49152 -> 2 CTAs/SM
    cudaFuncSetAttribute((const void*)gemm_fused<0>, cudaFuncAttributeMaxDynamicSharedMemorySize, SMEM);
    cudaFuncSetAttribute((const void*)gemm_fused<1>, cudaFuncAttributeMaxDynamicSharedMemorySize, SMEM);
    cudaFuncSetAttribute((const void*)gemm_fused<2>, cudaFuncAttributeMaxDynamicSharedMemorySize, SMEM);

    float* newh = (out_size >= B_ * (D_ + H_)) ? (out + (long)B_ * D_) : pnh;

    prologue<<<CONV_BLOCKS + 2 * TCONV_BIG, 256>>>(
        x, h, (__half*)pa1, (__half*)pa2, W_u, W_r, (__half*)pwu, (__half*)pwr);

    // GEMM1 (u fp16, rh fp16 into a2) + hidden tconv(W_g, W_up)
    gemm_fused<0><<<64 * 8 + 2 * TCONV_BIG, 256, SMEM>>>(
        (const __half*)pa1, C_,
        (const __half*)pwu, (const __half*)pwr, C_,
        b_u, b_r, h, nullptr, (__half*)pu, nullptr, (__half*)pa2,
        C_, 64, 8, 32, 1,
        W_g, W_up, (__half*)pwg, (__half*)pwp, C_, H_, TCONV_BIG);

    // GEMM2 (g fp16, up fp16) + hidden tconv(W_d)
    {
        const int tWd = (D_ / 32) * (H_ / 64);  // 2048
        gemm_fused<1><<<64 * 8 + tWd, 256, SMEM>>>(
            (const __half*)pa2, C_,
            (const __half*)pwg, (const __half*)pwp, C_,
            b_g, b_up, nullptr, nullptr, (__half*)pg, (__half*)pup, nullptr,
            C_, 64, 8, 32, 1,
            W_d, W_d, (__half*)pwd, (__half*)pwd, H_, D_, tWd);
    }

    ln_newh<<<B_, 256>>>((const __half*)pu, h, (const __half*)pg, (const __half*)pup,
                         g_hh, be_h, newh, (__half*)pa3);

    // down: new_h @ W_d (split-K x4, f32 partials)
    gemm_fused<2><<<8 * 8 * KSLICE_D, 256, SMEM>>>(
        (const __half*)pa3, H_,
        (const __half*)pwd, (const __half*)pwd, H_,
        b_d, b_d, nullptr, pdo, nullptr, nullptr, nullptr,
        H_, 8, 8, 1000, KSLICE_D,
        nullptr, nullptr, nullptr, nullptr, 1, 32, 0);

    ln_out<<<B_, 256>>>(pdo, b_d, g_o, be_o, out);
}

// round 16
// speedup vs baseline: 1.5082x; 1.5082x over previous
#include <cuda_runtime.h>
#include <cuda_fp16.h>
#include <math.h>
#include <stdint.h>

#define B_ 1024
#define D_ 1024
#define H_ 4096
#define C_ 5120
#define LN_EPS 1e-3f
#define KSLICE_D 4

// ---------------- scratch (device globals: allocation-free) ----------------
__device__ __align__(1024) __half g_a1[B_ * C_];
__device__ __align__(1024) __half g_a2[B_ * C_];
__device__ __align__(1024) __half g_a3[B_ * H_];
__device__ __align__(1024) __half g_wu[(long)H_ * C_];
__device__ __align__(1024) __half g_wr[(long)H_ * C_];
__device__ __align__(1024) __half g_wg[(long)H_ * C_];
__device__ __align__(1024) __half g_wp[(long)H_ * C_];
__device__ __align__(1024) __half g_wd[(long)D_ * H_];
__device__ float g_u [B_ * H_];
__device__ float g_g [B_ * H_];
__device__ float g_up[B_ * H_];
__device__ float g_nh[B_ * H_];
__device__ float g_do[KSLICE_D * B_ * D_];

// ---------------- helpers ----------------
__device__ __forceinline__ uint32_t smem_u32(const void* p) {
    uint32_t a;
    asm("{ .reg .u64 t; cvta.to.shared.u64 t, %1; cvt.u32.u64 %0, t; }" : "=r"(a) : "l"(p));
    return a;
}
__device__ __forceinline__ void cp16(uint32_t dst, const void* src) {
    asm volatile("cp.async.cg.shared.global [%0], [%1], 16;" :: "r"(dst), "l"(src) : "memory");
}
__device__ __forceinline__ void ldsm_x4(uint32_t* r, uint32_t addr) {
    asm volatile("ldmatrix.sync.aligned.m8n8.x4.shared.b16 {%0,%1,%2,%3}, [%4];"
                 : "=r"(r[0]), "=r"(r[1]), "=r"(r[2]), "=r"(r[3]) : "r"(addr));
}
__device__ __forceinline__ void mma_f32(float* c, const uint32_t* a, uint32_t b0, uint32_t b1) {
    asm volatile(
        "mma.sync.aligned.m16n8k16.row.col.f32.f16.f16.f32 "
        "{%0,%1,%2,%3}, {%4,%5,%6,%7}, {%8,%9}, {%0,%1,%2,%3};"
        : "+f"(c[0]), "+f"(c[1]), "+f"(c[2]), "+f"(c[3])
        : "r"(a[0]), "r"(a[1]), "r"(a[2]), "r"(a[3]), "r"(b0), "r"(b1));
}
__device__ __forceinline__ float sigm(float x) { return 1.0f / (1.0f + expf(-x)); }

// swizzled offset inside a [rows][32 fp16] tile (64B rows, 16B chunks) — R11-proven
__device__ __forceinline__ uint32_t sw_off(int row, int cb) {
    return (uint32_t)row * 64u + (uint32_t)((cb ^ ((row >> 1) & 3)) << 4);
}

// ---------------- shared tconv body (transpose + fp16 round, 64K x 32N tile) ----------------
__device__ __forceinline__ void tconv_body(const float* __restrict__ src,
                                           __half* __restrict__ dst,
                                           int kdim, int ndim, int idx, void* smem)
{
    float (*t)[33] = reinterpret_cast<float(*)[33]>(smem);
    const int nblk = ndim / 32;
    const int nb = (idx % nblk) * 32;
    const int kt = (idx / nblk) * 64;
    const int tid = threadIdx.x;
    const int c4 = (tid & 7) * 4, r0 = tid >> 3;
#pragma unroll
    for (int p = 0; p < 2; p++) {
        const int r = r0 + p * 32;
        const float4 f = *(const float4*)(src + (size_t)(kt + r) * ndim + nb + c4);
        t[r][c4] = f.x; t[r][c4 + 1] = f.y; t[r][c4 + 2] = f.z; t[r][c4 + 3] = f.w;
    }
    __syncthreads();
    const int n  = tid >> 3;
    const int k8 = (tid & 7) * 8;
    __half2 hv[4];
#pragma unroll
    for (int i = 0; i < 4; i++)
        hv[i] = __halves2half2(__float2half_rn(t[k8 + 2 * i][n]), __float2half_rn(t[k8 + 2 * i + 1][n]));
    const long o = (long)(nb + n) * kdim + kt + k8;
    *(uint4*)(dst + o) = make_uint4(*(uint32_t*)&hv[0], *(uint32_t*)&hv[1],
                                    *(uint32_t*)&hv[2], *(uint32_t*)&hv[3]);
}

// ---------------- single-term fp16 HMMA GEMM + piggyback tconv (R14 verbatim) ----------------
#define KT 32
#define STG 3
#define STAGE_BYTES 16384u

template<int MODE>
__global__ void __launch_bounds__(256, 2) gemm_fused(
    const __half* __restrict__ A, int ldA,
    const __half* __restrict__ B0, const __half* __restrict__ B1, int ldB,
    const float* __restrict__ bias0, const float* __restrict__ bias1,
    const float* __restrict__ hmul,
    float* __restrict__ fout0, float* __restrict__ fout1,
    __half* __restrict__ oba,
    int K, int ntx, int mty, int nhalf, int kslices,
    const float* __restrict__ ts0, const float* __restrict__ ts1,
    __half* __restrict__ td0, __half* __restrict__ td1,
    int tkdim, int tndim, int tPerW)
{
    extern __shared__ __align__(1024) char smraw[];
    const int gb = ntx * mty * kslices;
    const int bx = blockIdx.x;

    if (bx >= gb) {
        int idx = bx - gb;
        const float* src = ts0;
        __half* dst = td0;
        if (idx >= tPerW) { src = ts1; dst = td1; idx -= tPerW; }
        tconv_body(src, dst, tkdim, tndim, idx, smraw);
        return;
    }

    const uint32_t sb = smem_u32(smraw);
    const int tid = threadIdx.x, lane = tid & 31, wid = tid >> 5;
    const int wm = (wid >> 2) * 64;
    const int wn = (wid & 3) * 32;

    const int nt = bx % ntx;
    const int mt = (bx / ntx) % mty;
    const int kz = bx / (ntx * mty);
    const bool second = nt >= nhalf;
    const int ntin = second ? nt - nhalf : nt;
    const __half* Bp = second ? B1 : B0;
    const float* bias = second ? bias1 : bias0;

    const int m0 = mt * 128, n0 = ntin * 128;
    const int Ks = K / kslices;
    const int kbeg = kz * Ks;
    const int S = Ks / KT;

    const int lr  = tid >> 1;
    const int lcb = (tid & 1) * 2;
    auto load_stage = [&](int slot, int kk) {
        const uint32_t tb = sb + (uint32_t)slot * STAGE_BYTES;
        const size_t arow = (size_t)(m0 + lr) * ldA + kk;
        const size_t brow = (size_t)(n0 + lr) * ldB + kk;
#pragma unroll
        for (int c = 0; c < 2; c++) {
            const int cb = lcb + c;
            const uint32_t sw = tb + sw_off(lr, cb);
            cp16(sw,         A  + arow + cb * 8);
            cp16(sw + 8192,  Bp + brow + cb * 8);
        }
    };

    const int lb = (lane >> 4) & 1;
    uint32_t offA[4], offB[2];
#pragma unroll
    for (int i = 0; i < 4; i++) offA[i] = sw_off(wm + i * 16 + (lane & 15), lb);
#pragma unroll
    for (int jp = 0; jp < 2; jp++) offB[jp] = sw_off(wn + jp * 16 + (lane & 15), lb);

#pragma unroll
    for (int s = 0; s < STG - 1; s++) {
        if (s < S) load_stage(s, kbeg + s * KT);
        asm volatile("cp.async.commit_group;" ::: "memory");
    }

    float acc[4][4][4];
#pragma unroll
    for (int i = 0; i < 4; i++)
#pragma unroll
        for (int j = 0; j < 4; j++)
#pragma unroll
            for (int e = 0; e < 4; e++) acc[i][j][e] = 0.f;

    for (int ks = 0; ks < S; ks++) {
        asm volatile("cp.async.wait_group 1;" ::: "memory");
        __syncthreads();
        if (ks + STG - 1 < S) load_stage((ks + STG - 1) % STG, kbeg + (ks + STG - 1) * KT);
        asm volatile("cp.async.commit_group;" ::: "memory");

        const uint32_t base = sb + (uint32_t)(ks % STG) * STAGE_BYTES;
#pragma unroll
        for (int s = 0; s < 2; s++) {
            const uint32_t sx = (uint32_t)(s << 5);
            uint32_t a[4][4], b[2][4];
#pragma unroll
            for (int i = 0; i < 4; i++)   ldsm_x4(a[i], base + (offA[i] ^ sx));
#pragma unroll
            for (int jp = 0; jp < 2; jp++) ldsm_x4(b[jp], base + 8192 + (offB[jp] ^ sx));
#pragma unroll
            for (int i = 0; i < 4; i++)
#pragma unroll
                for (int j = 0; j < 4; j++)
                    mma_f32(acc[i][j], a[i], b[j >> 1][j & 1], b[j >> 1][2 | (j & 1)]);
        }
    }

    // ---- epilogue (R14 verbatim: f32 u/g/up) ----
#pragma unroll
    for (int i = 0; i < 4; i++) {
#pragma unroll
        for (int j = 0; j < 4; j++) {
            const int r0 = m0 + wm + i * 16 + (lane >> 2);
            const int gc = ntin * 128 + wn + j * 8 + 2 * (lane & 3);
#pragma unroll
            for (int half = 0; half < 2; half++) {
                const int row = r0 + half * 8;
                const float v0r = acc[i][j][half * 2];
                const float v1r = acc[i][j][half * 2 + 1];
                if (MODE == 0) {
                    const float v0 = v0r + bias[gc], v1 = v1r + bias[gc + 1];
                    if (!second) {
                        fout0[(long)row * H_ + gc]     = sigm(v0);
                        fout0[(long)row * H_ + gc + 1] = sigm(v1);
                    } else {
                        const float rh0 = sigm(v0) * hmul[(long)row * H_ + gc];
                        const float rh1 = sigm(v1) * hmul[(long)row * H_ + gc + 1];
                        oba[(long)row * C_ + D_ + gc]     = __float2half_rn(rh0);
                        oba[(long)row * C_ + D_ + gc + 1] = __float2half_rn(rh1);
                    }
                } else if (MODE == 1) {
                    float* dst = second ? fout1 : fout0;
                    dst[(long)row * H_ + gc]     = v0r + bias[gc];
                    dst[(long)row * H_ + gc + 1] = v1r + bias[gc + 1];
                } else {
                    float* dst = fout0 + (size_t)kz * B_ * D_;
                    dst[(long)row * D_ + gc]     = v0r;
                    dst[(long)row * D_ + gc + 1] = v1r;
                }
            }
        }
    }
}

// ---------------- prologue: conv_a1 blocks + tconv(W_u, W_r) blocks ----------------
#define CONV_BLOCKS (B_ * C_ / 4 / 256)       // 5120
#define TCONV_BIG   ((H_ / 32) * (C_ / 64))   // 10240

__global__ void __launch_bounds__(256, 2) prologue(
    const float* __restrict__ x, const float* __restrict__ h,
    __half* __restrict__ a1, __half* __restrict__ a2,
    const float* __restrict__ wu, const float* __restrict__ wr,
    __half* __restrict__ du, __half* __restrict__ dr)
{
    __shared__ float t[64][33];
    const int bx = blockIdx.x;
    if (bx < CONV_BLOCKS) {
        const long i4 = (long)bx * 256 + threadIdx.x;
        const int row = (int)(i4 / (C_ / 4));
        const int c = (int)(i4 % (C_ / 4)) * 4;
        float4 f;
        if (c < D_) f = *(const float4*)(x + (long)row * D_ + c);
        else        f = *(const float4*)(h + (long)row * H_ + (c - D_));
        __half2 hv0 = __halves2half2(__float2half_rn(f.x), __float2half_rn(f.y));
        __half2 hv1 = __halves2half2(__float2half_rn(f.z), __float2half_rn(f.w));
        const long o = (long)row * C_ + c;
        *(uint2*)(a1 + o) = make_uint2(*(uint32_t*)&hv0, *(uint32_t*)&hv1);
        if (c < D_)
            *(uint2*)(a2 + o) = make_uint2(*(uint32_t*)&hv0, *(uint32_t*)&hv1);
        return;
    }
    int idx = bx - CONV_BLOCKS;
    const float* src = wu;
    __half* dst = du;
    if (idx >= TCONV_BIG) { src = wr; dst = dr; idx -= TCONV_BIG; }
    tconv_body(src, dst, C_, H_, idx, t);
}

// ---------------- LayerNorm kernels (float4-vectorized; f32 inputs) ----------------
__global__ void ln_newh(const float* __restrict__ u, const float* __restrict__ h,
                        const float* __restrict__ g, const float* __restrict__ up,
                        const float* __restrict__ gamma, const float* __restrict__ beta,
                        float* __restrict__ out, __half* __restrict__ a3)
{
    const int row = blockIdx.x, tid = threadIdx.x;
    const long base = (long)row * H_;
    float v[16];
    float s = 0.f, ss = 0.f;
#pragma unroll
    for (int i = 0; i < 4; i++) {
        const int c = (i * 256 + tid) * 4;
        const float4 uu = *(const float4*)(u + base + c);
        const float4 hh = *(const float4*)(h + base + c);
        const float4 gg = *(const float4*)(g + base + c);
        const float4 pp = *(const float4*)(up + base + c);
        const float uf[4] = {uu.x, uu.y, uu.z, uu.w};
        const float hf[4] = {hh.x, hh.y, hh.z, hh.w};
        const float gf[4] = {gg.x, gg.y, gg.z, gg.w};
        const float pf[4] = {pp.x, pp.y, pp.z, pp.w};
#pragma unroll
        for (int e = 0; e < 4; e++) {
            const float val = hf[e] * (2.f - uf[e]) + uf[e] * (gf[e] * sigm(gf[e])) * pf[e];
            v[i * 4 + e] = val;
            s += val; ss += val * val;
        }
    }
    __shared__ float sm[2][8];
#pragma unroll
    for (int o = 16; o > 0; o >>= 1) {
        s  += __shfl_xor_sync(0xffffffffu, s, o);
        ss += __shfl_xor_sync(0xffffffffu, ss, o);
    }
    const int warp = tid >> 5, lane = tid & 31;
    if (lane == 0) { sm[0][warp] = s; sm[1][warp] = ss; }
    __syncthreads();
    float ts = 0.f, tss = 0.f;
#pragma unroll
    for (int w = 0; w < 8; w++) { ts += sm[0][w]; tss += sm[1][w]; }
    const float mean = ts / (float)H_;
    const float var  = tss / (float)H_ - mean * mean;
    const float rstd = rsqrtf(var + LN_EPS);
#pragma unroll
    for (int i = 0; i < 4; i++) {
        const int c = (i * 256 + tid) * 4;
        const float4 gm = *(const float4*)(gamma + c);
        const float4 bt = *(const float4*)(beta + c);
        float4 r;
        r.x = (v[i * 4 + 0] - mean) * rstd * gm.x + bt.x;
        r.y = (v[i * 4 + 1] - mean) * rstd * gm.y + bt.y;
        r.z = (v[i * 4 + 2] - mean) * rstd * gm.z + bt.z;
        r.w = (v[i * 4 + 3] - mean) * rstd * gm.w + bt.w;
        *(float4*)(out + base + c) = r;
        __half2 h0 = __halves2half2(__float2half_rn(r.x), __float2half_rn(r.y));
        __half2 h1 = __halves2half2(__float2half_rn(r.z), __float2half_rn(r.w));
        *(uint2*)(a3 + base + c) = make_uint2(*(uint32_t*)&h0, *(uint32_t*)&h1);
    }
}

__global__ void ln_out(const float* __restrict__ in,
                       const float* __restrict__ bd,
                       const float* __restrict__ gamma, const float* __restrict__ beta,
                       float* __restrict__ out)
{
    const int row = blockIdx.x, tid = threadIdx.x;
    const long base = (long)row * D_;
    const long zoff = (long)B_ * D_;
    const int c = tid * 4;
    float4 val = *(const float4*)(bd + c);
#pragma unroll
    for (int z = 0; z < KSLICE_D; z++) {
        const float4 p = *(const float4*)(in + z * zoff + base + c);
        val.x += p.x; val.y += p.y; val.z += p.z; val.w += p.w;
    }
    float s = val.x + val.y + val.z + val.w;
    float ss = val.x * val.x + val.y * val.y + val.z * val.z + val.w * val.w;
    __shared__ float sm[2][8];
#pragma unroll
    for (int o = 16; o > 0; o >>= 1) {
        s  += __shfl_xor_sync(0xffffffffu, s, o);
        ss += __shfl_xor_sync(0xffffffffu, ss, o);
    }
    const int warp = tid >> 5, lane = tid & 31;
    if (lane == 0) { sm[0][warp] = s; sm[1][warp] = ss; }
    __syncthreads();
    float ts = 0.f, tss = 0.f;
#pragma unroll
    for (int w = 0; w < 8; w++) { ts += sm[0][w]; tss += sm[1][w]; }
    const float mean = ts / (float)D_;
    const float var  = tss / (float)D_ - mean * mean;
    const float rstd = rsqrtf(var + LN_EPS);
    const float4 gm = *(const float4*)(gamma + c);
    const float4 bt = *(const float4*)(beta + c);
    float4 r;
    r.x = (val.x - mean) * rstd * gm.x + bt.x;
    r.y = (val.y - mean) * rstd * gm.y + bt.y;
    r.z = (val.z - mean) * rstd * gm.z + bt.z;
    r.w = (val.w - mean) * rstd * gm.w + bt.w;
    *(float4*)(out + base + c) = r;
}

// ---------------- host ----------------
extern "C" void kernel_launch(void* const* d_in, const int* in_sizes, int n_in,
                              void* d_out, int out_size)
{
    const float* x    = (const float*)d_in[0];
    const float* h    = (const float*)d_in[1];
    const float* W_u  = (const float*)d_in[2];
    const float* b_u  = (const float*)d_in[3];
    const float* W_r  = (const float*)d_in[4];
    const float* b_r  = (const float*)d_in[5];
    const float* W_g  = (const float*)d_in[6];
    const float* b_g  = (const float*)d_in[7];
    const float* W_up = (const float*)d_in[8];
    const float* b_up = (const float*)d_in[9];
    const float* W_d  = (const float*)d_in[10];
    const float* b_d  = (const float*)d_in[11];
    const float* g_hh = (const float*)d_in[12];
    const float* be_h = (const float*)d_in[13];
    const float* g_o  = (const float*)d_in[14];
    const float* be_o = (const float*)d_in[15];
    float* out = (float*)d_out;

    void *pa1, *pa2, *pa3, *pwu, *pwr, *pwg, *pwp, *pwd;
    float *pu, *pg, *pup, *pnh, *pdo;
    cudaGetSymbolAddress(&pa1, g_a1);
    cudaGetSymbolAddress(&pa2, g_a2);
    cudaGetSymbolAddress(&pa3, g_a3);
    cudaGetSymbolAddress(&pwu, g_wu); cudaGetSymbolAddress(&pwr, g_wr);
    cudaGetSymbolAddress(&pwg, g_wg); cudaGetSymbolAddress(&pwp, g_wp);
    cudaGetSymbolAddress(&pwd, g_wd);
    cudaGetSymbolAddress((void**)&pu,  g_u);
    cudaGetSymbolAddress((void**)&pg,  g_g);
    cudaGetSymbolAddress((void**)&pup, g_up);
    cudaGetSymbolAddress((void**)&pnh, g_nh);
    cudaGetSymbolAddress((void**)&pdo, g_do);

    constexpr int SMEM = STG * (int)STAGE_BYTES;  // 49152 -> 2 CTAs/SM
    cudaFuncSetAttribute((const void*)gemm_fused<0>, cudaFuncAttributeMaxDynamicSharedMemorySize, SMEM);
    cudaFuncSetAttribute((const void*)gemm_fused<1>, cudaFuncAttributeMaxDynamicSharedMemorySize, SMEM);
    cudaFuncSetAttribute((const void*)gemm_fused<2>, cudaFuncAttributeMaxDynamicSharedMemorySize, SMEM);

    float* newh = (out_size >= B_ * (D_ + H_)) ? (out + (long)B_ * D_) : pnh;

    // prologue: conv_a1 + tconv(W_u) + tconv(W_r), one launch
    prologue<<<CONV_BLOCKS + 2 * TCONV_BIG, 256>>>(
        x, h, (__half*)pa1, (__half*)pa2, W_u, W_r, (__half*)pwu, (__half*)pwr);

    // GEMM1 (u, rh) + hidden tconv(W_g, W_up)
    gemm_fused<0><<<64 * 8 + 2 * TCONV_BIG, 256, SMEM>>>(
        (const __half*)pa1, C_,
        (const __half*)pwu, (const __half*)pwr, C_,
        b_u, b_r, h, pu, nullptr, (__half*)pa2,
        C_, 64, 8, 32, 1,
        W_g, W_up, (__half*)pwg, (__half*)pwp, C_, H_, TCONV_BIG);

    // GEMM2 (g, up) + hidden tconv(W_d)
    {
        const int tWd = (D_ / 32) * (H_ / 64);  // 2048
        gemm_fused<1><<<64 * 8 + tWd, 256, SMEM>>>(
            (const __half*)pa2, C_,
            (const __half*)pwg, (const __half*)pwp, C_,
            b_g, b_up, nullptr, pg, pup, nullptr,
            C_, 64, 8, 32, 1,
            W_d, W_d, (__half*)pwd, (__half*)pwd, H_, D_, tWd);
    }

    ln_newh<<<B_, 256>>>(pu, h, pg, pup, g_hh, be_h, newh, (__half*)pa3);

    // down: new_h @ W_d (split-K x4)
    gemm_fused<2><<<8 * 8 * KSLICE_D, 256, SMEM>>>(
        (const __half*)pa3, H_,
        (const __half*)pwd, (const __half*)pwd, H_,
        b_d, b_d, nullptr, pdo, nullptr, nullptr,
        H_, 8, 8, 1000, KSLICE_D,
        nullptr, nullptr, nullptr, nullptr, 1, 32, 0);

    ln_out<<<B_, 256>>>(pdo, b_d, g_o, be_o, out);
}

// round 17
// speedup vs baseline: 1.5128x; 1.0031x over previous
#include <cuda_runtime.h>
#include <cuda_fp16.h>
#include <math.h>
#include <stdint.h>

#define B_ 1024
#define D_ 1024
#define H_ 4096
#define C_ 5120
#define LN_EPS 1e-3f
#define KSLICE_D 4

// ---------------- scratch (device globals: allocation-free) ----------------
__device__ __align__(1024) __half g_a1[B_ * C_];
__device__ __align__(1024) __half g_a2[B_ * C_];
__device__ __align__(1024) __half g_a3[B_ * H_];
__device__ __align__(1024) __half g_wu[(long)H_ * C_];
__device__ __align__(1024) __half g_wr[(long)H_ * C_];
__device__ __align__(1024) __half g_wg[(long)H_ * C_];
__device__ __align__(1024) __half g_wp[(long)H_ * C_];
__device__ __align__(1024) __half g_wd[(long)D_ * H_];
__device__ float g_u [B_ * H_];
__device__ float g_g [B_ * H_];
__device__ float g_up[B_ * H_];
__device__ float g_nh[B_ * H_];
__device__ float g_do[KSLICE_D * B_ * D_];

// ---------------- helpers ----------------
__device__ __forceinline__ uint32_t smem_u32(const void* p) {
    uint32_t a;
    asm("{ .reg .u64 t; cvta.to.shared.u64 t, %1; cvt.u32.u64 %0, t; }" : "=r"(a) : "l"(p));
    return a;
}
__device__ __forceinline__ void cp16(uint32_t dst, const void* src) {
    asm volatile("cp.async.cg.shared.global [%0], [%1], 16;" :: "r"(dst), "l"(src) : "memory");
}
__device__ __forceinline__ void ldsm_x4(uint32_t* r, uint32_t addr) {
    asm volatile("ldmatrix.sync.aligned.m8n8.x4.shared.b16 {%0,%1,%2,%3}, [%4];"
                 : "=r"(r[0]), "=r"(r[1]), "=r"(r[2]), "=r"(r[3]) : "r"(addr));
}
__device__ __forceinline__ void mma_f32(float* c, const uint32_t* a, uint32_t b0, uint32_t b1) {
    asm volatile(
        "mma.sync.aligned.m16n8k16.row.col.f32.f16.f16.f32 "
        "{%0,%1,%2,%3}, {%4,%5,%6,%7}, {%8,%9}, {%0,%1,%2,%3};"
        : "+f"(c[0]), "+f"(c[1]), "+f"(c[2]), "+f"(c[3])
        : "r"(a[0]), "r"(a[1]), "r"(a[2]), "r"(a[3]), "r"(b0), "r"(b1));
}
__device__ __forceinline__ float sigm(float x) { return 1.0f / (1.0f + expf(-x)); }

// swizzled offset inside a [rows][32 fp16] tile (64B rows, 16B chunks) — R11-proven
__device__ __forceinline__ uint32_t sw_off(int row, int cb) {
    return (uint32_t)row * 64u + (uint32_t)((cb ^ ((row >> 1) & 3)) << 4);
}

// ---------------- shared tconv body (transpose + fp16 round, 64K x 32N tile) ----------------
__device__ __forceinline__ void tconv_body(const float* __restrict__ src,
                                           __half* __restrict__ dst,
                                           int kdim, int ndim, int idx, void* smem)
{
    float (*t)[33] = reinterpret_cast<float(*)[33]>(smem);
    const int nblk = ndim / 32;
    const int nb = (idx % nblk) * 32;
    const int kt = (idx / nblk) * 64;
    const int tid = threadIdx.x;
    const int c4 = (tid & 7) * 4, r0 = tid >> 3;
#pragma unroll
    for (int p = 0; p < 2; p++) {
        const int r = r0 + p * 32;
        const float4 f = *(const float4*)(src + (size_t)(kt + r) * ndim + nb + c4);
        t[r][c4] = f.x; t[r][c4 + 1] = f.y; t[r][c4 + 2] = f.z; t[r][c4 + 3] = f.w;
    }
    __syncthreads();
    const int n  = tid >> 3;
    const int k8 = (tid & 7) * 8;
    __half2 hv[4];
#pragma unroll
    for (int i = 0; i < 4; i++)
        hv[i] = __halves2half2(__float2half_rn(t[k8 + 2 * i][n]), __float2half_rn(t[k8 + 2 * i + 1][n]));
    const long o = (long)(nb + n) * kdim + kt + k8;
    *(uint4*)(dst + o) = make_uint4(*(uint32_t*)&hv[0], *(uint32_t*)&hv[1],
                                    *(uint32_t*)&hv[2], *(uint32_t*)&hv[3]);
}

// ---------------- single-term fp16 HMMA GEMM + piggyback tconv (R14/R16 verbatim) ----------------
#define KT 32
#define STG 3
#define STAGE_BYTES 16384u

template<int MODE>
__global__ void __launch_bounds__(256, 2) gemm_fused(
    const __half* __restrict__ A, int ldA,
    const __half* __restrict__ B0, const __half* __restrict__ B1, int ldB,
    const float* __restrict__ bias0, const float* __restrict__ bias1,
    const float* __restrict__ hmul,
    float* __restrict__ fout0, float* __restrict__ fout1,
    __half* __restrict__ oba,
    int K, int ntx, int mty, int nhalf, int kslices,
    const float* __restrict__ ts0, const float* __restrict__ ts1,
    __half* __restrict__ td0, __half* __restrict__ td1,
    int tkdim, int tndim, int tPerW)
{
    extern __shared__ __align__(1024) char smraw[];
    const int gb = ntx * mty * kslices;
    const int bx = blockIdx.x;

    if (bx >= gb) {
        int idx = bx - gb;
        const float* src = ts0;
        __half* dst = td0;
        if (idx >= tPerW) { src = ts1; dst = td1; idx -= tPerW; }
        tconv_body(src, dst, tkdim, tndim, idx, smraw);
        return;
    }

    const uint32_t sb = smem_u32(smraw);
    const int tid = threadIdx.x, lane = tid & 31, wid = tid >> 5;
    const int wm = (wid >> 2) * 64;
    const int wn = (wid & 3) * 32;

    const int nt = bx % ntx;
    const int mt = (bx / ntx) % mty;
    const int kz = bx / (ntx * mty);
    const bool second = nt >= nhalf;
    const int ntin = second ? nt - nhalf : nt;
    const __half* Bp = second ? B1 : B0;
    const float* bias = second ? bias1 : bias0;

    const int m0 = mt * 128, n0 = ntin * 128;
    const int Ks = K / kslices;
    const int kbeg = kz * Ks;
    const int S = Ks / KT;

    const int lr  = tid >> 1;
    const int lcb = (tid & 1) * 2;
    auto load_stage = [&](int slot, int kk) {
        const uint32_t tb = sb + (uint32_t)slot * STAGE_BYTES;
        const size_t arow = (size_t)(m0 + lr) * ldA + kk;
        const size_t brow = (size_t)(n0 + lr) * ldB + kk;
#pragma unroll
        for (int c = 0; c < 2; c++) {
            const int cb = lcb + c;
            const uint32_t sw = tb + sw_off(lr, cb);
            cp16(sw,         A  + arow + cb * 8);
            cp16(sw + 8192,  Bp + brow + cb * 8);
        }
    };

    const int lb = (lane >> 4) & 1;
    uint32_t offA[4], offB[2];
#pragma unroll
    for (int i = 0; i < 4; i++) offA[i] = sw_off(wm + i * 16 + (lane & 15), lb);
#pragma unroll
    for (int jp = 0; jp < 2; jp++) offB[jp] = sw_off(wn + jp * 16 + (lane & 15), lb);

#pragma unroll
    for (int s = 0; s < STG - 1; s++) {
        if (s < S) load_stage(s, kbeg + s * KT);
        asm volatile("cp.async.commit_group;" ::: "memory");
    }

    float acc[4][4][4];
#pragma unroll
    for (int i = 0; i < 4; i++)
#pragma unroll
        for (int j = 0; j < 4; j++)
#pragma unroll
            for (int e = 0; e < 4; e++) acc[i][j][e] = 0.f;

    for (int ks = 0; ks < S; ks++) {
        asm volatile("cp.async.wait_group 1;" ::: "memory");
        __syncthreads();
        if (ks + STG - 1 < S) load_stage((ks + STG - 1) % STG, kbeg + (ks + STG - 1) * KT);
        asm volatile("cp.async.commit_group;" ::: "memory");

        const uint32_t base = sb + (uint32_t)(ks % STG) * STAGE_BYTES;
#pragma unroll
        for (int s = 0; s < 2; s++) {
            const uint32_t sx = (uint32_t)(s << 5);
            uint32_t a[4][4], b[2][4];
#pragma unroll
            for (int i = 0; i < 4; i++)   ldsm_x4(a[i], base + (offA[i] ^ sx));
#pragma unroll
            for (int jp = 0; jp < 2; jp++) ldsm_x4(b[jp], base + 8192 + (offB[jp] ^ sx));
#pragma unroll
            for (int i = 0; i < 4; i++)
#pragma unroll
                for (int j = 0; j < 4; j++)
                    mma_f32(acc[i][j], a[i], b[j >> 1][j & 1], b[j >> 1][2 | (j & 1)]);
        }
    }

    // ---- epilogue (R14 verbatim: f32 u/g/up) ----
#pragma unroll
    for (int i = 0; i < 4; i++) {
#pragma unroll
        for (int j = 0; j < 4; j++) {
            const int r0 = m0 + wm + i * 16 + (lane >> 2);
            const int gc = ntin * 128 + wn + j * 8 + 2 * (lane & 3);
#pragma unroll
            for (int half = 0; half < 2; half++) {
                const int row = r0 + half * 8;
                const float v0r = acc[i][j][half * 2];
                const float v1r = acc[i][j][half * 2 + 1];
                if (MODE == 0) {
                    const float v0 = v0r + bias[gc], v1 = v1r + bias[gc + 1];
                    if (!second) {
                        fout0[(long)row * H_ + gc]     = sigm(v0);
                        fout0[(long)row * H_ + gc + 1] = sigm(v1);
                    } else {
                        const float rh0 = sigm(v0) * hmul[(long)row * H_ + gc];
                        const float rh1 = sigm(v1) * hmul[(long)row * H_ + gc + 1];
                        oba[(long)row * C_ + D_ + gc]     = __float2half_rn(rh0);
                        oba[(long)row * C_ + D_ + gc + 1] = __float2half_rn(rh1);
                    }
                } else if (MODE == 1) {
                    float* dst = second ? fout1 : fout0;
                    dst[(long)row * H_ + gc]     = v0r + bias[gc];
                    dst[(long)row * H_ + gc + 1] = v1r + bias[gc + 1];
                } else {
                    float* dst = fout0 + (size_t)kz * B_ * D_;
                    dst[(long)row * D_ + gc]     = v0r;
                    dst[(long)row * D_ + gc + 1] = v1r;
                }
            }
        }
    }
}

// ---------------- prologue: conv_a1 blocks + tconv(W_u, W_r) blocks ----------------
#define CONV_BLOCKS (B_ * C_ / 4 / 256)       // 5120
#define TCONV_BIG   ((H_ / 32) * (C_ / 64))   // 10240

__global__ void __launch_bounds__(256, 2) prologue(
    const float* __restrict__ x, const float* __restrict__ h,
    __half* __restrict__ a1, __half* __restrict__ a2,
    const float* __restrict__ wu, const float* __restrict__ wr,
    __half* __restrict__ du, __half* __restrict__ dr)
{
    __shared__ float t[64][33];
    const int bx = blockIdx.x;
    if (bx < CONV_BLOCKS) {
        const long i4 = (long)bx * 256 + threadIdx.x;
        const int row = (int)(i4 / (C_ / 4));
        const int c = (int)(i4 % (C_ / 4)) * 4;
        float4 f;
        if (c < D_) f = *(const float4*)(x + (long)row * D_ + c);
        else        f = *(const float4*)(h + (long)row * H_ + (c - D_));
        __half2 hv0 = __halves2half2(__float2half_rn(f.x), __float2half_rn(f.y));
        __half2 hv1 = __halves2half2(__float2half_rn(f.z), __float2half_rn(f.w));
        const long o = (long)row * C_ + c;
        *(uint2*)(a1 + o) = make_uint2(*(uint32_t*)&hv0, *(uint32_t*)&hv1);
        if (c < D_)
            *(uint2*)(a2 + o) = make_uint2(*(uint32_t*)&hv0, *(uint32_t*)&hv1);
        return;
    }
    int idx = bx - CONV_BLOCKS;
    const float* src = wu;
    __half* dst = du;
    if (idx >= TCONV_BIG) { src = wr; dst = dr; idx -= TCONV_BIG; }
    tconv_body(src, dst, C_, H_, idx, t);
}

// ---------------- LayerNorm kernels ----------------
// ln_newh: 512 threads/row for doubled MLP; each thread 2 float4 per stream.
__global__ void ln_newh(const float* __restrict__ u, const float* __restrict__ h,
                        const float* __restrict__ g, const float* __restrict__ up,
                        const float* __restrict__ gamma, const float* __restrict__ beta,
                        float* __restrict__ out, __half* __restrict__ a3)
{
    const int row = blockIdx.x, tid = threadIdx.x;
    const long base = (long)row * H_;
    float v[8];
    float s = 0.f, ss = 0.f;
#pragma unroll
    for (int i = 0; i < 2; i++) {
        const int c = (i * 512 + tid) * 4;
        const float4 uu = *(const float4*)(u + base + c);
        const float4 hh = *(const float4*)(h + base + c);
        const float4 gg = *(const float4*)(g + base + c);
        const float4 pp = *(const float4*)(up + base + c);
        const float uf[4] = {uu.x, uu.y, uu.z, uu.w};
        const float hf[4] = {hh.x, hh.y, hh.z, hh.w};
        const float gf[4] = {gg.x, gg.y, gg.z, gg.w};
        const float pf[4] = {pp.x, pp.y, pp.z, pp.w};
#pragma unroll
        for (int e = 0; e < 4; e++) {
            const float val = hf[e] * (2.f - uf[e]) + uf[e] * (gf[e] * sigm(gf[e])) * pf[e];
            v[i * 4 + e] = val;
            s += val; ss += val * val;
        }
    }
    __shared__ float sm[2][16];
#pragma unroll
    for (int o = 16; o > 0; o >>= 1) {
        s  += __shfl_xor_sync(0xffffffffu, s, o);
        ss += __shfl_xor_sync(0xffffffffu, ss, o);
    }
    const int warp = tid >> 5, lane = tid & 31;
    if (lane == 0) { sm[0][warp] = s; sm[1][warp] = ss; }
    __syncthreads();
    float ts = 0.f, tss = 0.f;
#pragma unroll
    for (int w = 0; w < 16; w++) { ts += sm[0][w]; tss += sm[1][w]; }
    const float mean = ts / (float)H_;
    const float var  = tss / (float)H_ - mean * mean;
    const float rstd = rsqrtf(var + LN_EPS);
#pragma unroll
    for (int i = 0; i < 2; i++) {
        const int c = (i * 512 + tid) * 4;
        const float4 gm = *(const float4*)(gamma + c);
        const float4 bt = *(const float4*)(beta + c);
        float4 r;
        r.x = (v[i * 4 + 0] - mean) * rstd * gm.x + bt.x;
        r.y = (v[i * 4 + 1] - mean) * rstd * gm.y + bt.y;
        r.z = (v[i * 4 + 2] - mean) * rstd * gm.z + bt.z;
        r.w = (v[i * 4 + 3] - mean) * rstd * gm.w + bt.w;
        *(float4*)(out + base + c) = r;
        __half2 h0 = __halves2half2(__float2half_rn(r.x), __float2half_rn(r.y));
        __half2 h1 = __halves2half2(__float2half_rn(r.z), __float2half_rn(r.w));
        *(uint2*)(a3 + base + c) = make_uint2(*(uint32_t*)&h0, *(uint32_t*)&h1);
    }
}

__global__ void ln_out(const float* __restrict__ in,
                       const float* __restrict__ bd,
                       const float* __restrict__ gamma, const float* __restrict__ beta,
                       float* __restrict__ out)
{
    const int row = blockIdx.x, tid = threadIdx.x;
    const long base = (long)row * D_;
    const long zoff = (long)B_ * D_;
    const int c = tid * 4;
    float4 val = *(const float4*)(bd + c);
#pragma unroll
    for (int z = 0; z < KSLICE_D; z++) {
        const float4 p = *(const float4*)(in + z * zoff + base + c);
        val.x += p.x; val.y += p.y; val.z += p.z; val.w += p.w;
    }
    float s = val.x + val.y + val.z + val.w;
    float ss = val.x * val.x + val.y * val.y + val.z * val.z + val.w * val.w;
    __shared__ float sm[2][8];
#pragma unroll
    for (int o = 16; o > 0; o >>= 1) {
        s  += __shfl_xor_sync(0xffffffffu, s, o);
        ss += __shfl_xor_sync(0xffffffffu, ss, o);
    }
    const int warp = tid >> 5, lane = tid & 31;
    if (lane == 0) { sm[0][warp] = s; sm[1][warp] = ss; }
    __syncthreads();
    float ts = 0.f, tss = 0.f;
#pragma unroll
    for (int w = 0; w < 8; w++) { ts += sm[0][w]; tss += sm[1][w]; }
    const float mean = ts / (float)D_;
    const float var  = tss / (float)D_ - mean * mean;
    const float rstd = rsqrtf(var + LN_EPS);
    const float4 gm = *(const float4*)(gamma + c);
    const float4 bt = *(const float4*)(beta + c);
    float4 r;
    r.x = (val.x - mean) * rstd * gm.x + bt.x;
    r.y = (val.y - mean) * rstd * gm.y + bt.y;
    r.z = (val.z - mean) * rstd * gm.z + bt.z;
    r.w = (val.w - mean) * rstd * gm.w + bt.w;
    *(float4*)(out + base + c) = r;
}

// ---------------- host ----------------
extern "C" void kernel_launch(void* const* d_in, const int* in_sizes, int n_in,
                              void* d_out, int out_size)
{
    const float* x    = (const float*)d_in[0];
    const float* h    = (const float*)d_in[1];
    const float* W_u  = (const float*)d_in[2];
    const float* b_u  = (const float*)d_in[3];
    const float* W_r  = (const float*)d_in[4];
    const float* b_r  = (const float*)d_in[5];
    const float* W_g  = (const float*)d_in[6];
    const float* b_g  = (const float*)d_in[7];
    const float* W_up = (const float*)d_in[8];
    const float* b_up = (const float*)d_in[9];
    const float* W_d  = (const float*)d_in[10];
    const float* b_d  = (const float*)d_in[11];
    const float* g_hh = (const float*)d_in[12];
    const float* be_h = (const float*)d_in[13];
    const float* g_o  = (const float*)d_in[14];
    const float* be_o = (const float*)d_in[15];
    float* out = (float*)d_out;

    void *pa1, *pa2, *pa3, *pwu, *pwr, *pwg, *pwp, *pwd;
    float *pu, *pg, *pup, *pnh, *pdo;
    cudaGetSymbolAddress(&pa1, g_a1);
    cudaGetSymbolAddress(&pa2, g_a2);
    cudaGetSymbolAddress(&pa3, g_a3);
    cudaGetSymbolAddress(&pwu, g_wu); cudaGetSymbolAddress(&pwr, g_wr);
    cudaGetSymbolAddress(&pwg, g_wg); cudaGetSymbolAddress(&pwp, g_wp);
    cudaGetSymbolAddress(&pwd, g_wd);
    cudaGetSymbolAddress((void**)&pu,  g_u);
    cudaGetSymbolAddress((void**)&pg,  g_g);
    cudaGetSymbolAddress((void**)&pup, g_up);
    cudaGetSymbolAddress((void**)&pnh, g_nh);
    cudaGetSymbolAddress((void**)&pdo, g_do);

    constexpr int SMEM = STG * (int)STAGE_BYTES;  // 49152 -> 2 CTAs/SM
    cudaFuncSetAttribute((const void*)gemm_fused<0>, cudaFuncAttributeMaxDynamicSharedMemorySize, SMEM);
    cudaFuncSetAttribute((const void*)gemm_fused<1>, cudaFuncAttributeMaxDynamicSharedMemorySize, SMEM);
    cudaFuncSetAttribute((const void*)gemm_fused<2>, cudaFuncAttributeMaxDynamicSharedMemorySize, SMEM);

    float* newh = (out_size >= B_ * (D_ + H_)) ? (out + (long)B_ * D_) : pnh;

    // prologue: conv_a1 + tconv(W_u) + tconv(W_r), one launch
    prologue<<<CONV_BLOCKS + 2 * TCONV_BIG, 256>>>(
        x, h, (__half*)pa1, (__half*)pa2, W_u, W_r, (__half*)pwu, (__half*)pwr);

    // GEMM1 (u, rh) + hidden tconv(W_g, W_up)
    gemm_fused<0><<<64 * 8 + 2 * TCONV_BIG, 256, SMEM>>>(
        (const __half*)pa1, C_,
        (const __half*)pwu, (const __half*)pwr, C_,
        b_u, b_r, h, pu, nullptr, (__half*)pa2,
        C_, 64, 8, 32, 1,
        W_g, W_up, (__half*)pwg, (__half*)pwp, C_, H_, TCONV_BIG);

    // GEMM2 (g, up) + hidden tconv(W_d)
    {
        const int tWd = (D_ / 32) * (H_ / 64);  // 2048
        gemm_fused<1><<<64 * 8 + tWd, 256, SMEM>>>(
            (const __half*)pa2, C_,
            (const __half*)pwg, (const __half*)pwp, C_,
            b_g, b_up, nullptr, pg, pup, nullptr,
            C_, 64, 8, 32, 1,
            W_d, W_d, (__half*)pwd, (__half*)pwd, H_, D_, tWd);
    }

    ln_newh<<<B_, 512>>>(pu, h, pg, pup, g_hh, be_h, newh, (__half*)pa3);

    // down: new_h @ W_d (split-K x4)
    gemm_fused<2><<<8 * 8 * KSLICE_D, 256, SMEM>>>(
        (const __half*)pa3, H_,
        (const __half*)pwd, (const __half*)pwd, H_,
        b_d, b_d, nullptr, pdo, nullptr, nullptr,
        H_, 8, 8, 1000, KSLICE_D,
        nullptr, nullptr, nullptr, nullptr, 1, 32, 0);

    ln_out<<<B_, 256>>>(pdo, b_d, g_o, be_o, out);
}